// round 1
// baseline (speedup 1.0000x reference)
#include <cuda_runtime.h>
#include <cstdint>

#define NTOK 32768
#define DM 1024
#define HD 1024
#define NE 8

// ---------------- device scratch (no allocations allowed) ----------------
__device__ int   g_count[NE];
__device__ int   g_offsets[NE];
__device__ int   g_tokens[NE][NTOK];
__device__ float g_scales[NE][NTOK];
__device__ float g_h[(size_t)2 * NTOK * HD];   // 256 MiB fp32 hidden scratch

// ---------------- helpers ----------------
__device__ __forceinline__ unsigned f2tf(float v) {
    unsigned o;
    asm("cvt.rna.tf32.f32 %0, %1;" : "=r"(o) : "f"(v));
    return o;
}

__device__ __forceinline__ void mma8(float* c, const unsigned* a, const unsigned* b) {
    asm volatile(
        "mma.sync.aligned.m16n8k8.row.col.f32.tf32.tf32.f32 "
        "{%0,%1,%2,%3}, {%4,%5,%6,%7}, {%8,%9}, {%0,%1,%2,%3};\n"
        : "+f"(c[0]), "+f"(c[1]), "+f"(c[2]), "+f"(c[3])
        : "r"(a[0]), "r"(a[1]), "r"(a[2]), "r"(a[3]), "r"(b[0]), "r"(b[1]));
}

// ---------------- init ----------------
__global__ void init_kernel() {
    if (threadIdx.x < NE) g_count[threadIdx.x] = 0;
}

// ---------------- gating: one warp per token ----------------
__global__ void gate_kernel(const float* __restrict__ x,
                            const float* __restrict__ gw,
                            const float* __restrict__ gb) {
    int gwid = (blockIdx.x * blockDim.x + threadIdx.x) >> 5;
    int lane = threadIdx.x & 31;
    if (gwid >= NTOK) return;
    const float* xr = x + (size_t)gwid * DM;

    float acc[NE];
#pragma unroll
    for (int e = 0; e < NE; e++) acc[e] = 0.f;

    for (int d = lane; d < DM; d += 32) {
        float xv = __ldg(xr + d);
        const float4* w4 = (const float4*)(gw + d * NE);
        float4 w0 = __ldg(w4);
        float4 w1 = __ldg(w4 + 1);
        acc[0] = fmaf(xv, w0.x, acc[0]);
        acc[1] = fmaf(xv, w0.y, acc[1]);
        acc[2] = fmaf(xv, w0.z, acc[2]);
        acc[3] = fmaf(xv, w0.w, acc[3]);
        acc[4] = fmaf(xv, w1.x, acc[4]);
        acc[5] = fmaf(xv, w1.y, acc[5]);
        acc[6] = fmaf(xv, w1.z, acc[6]);
        acc[7] = fmaf(xv, w1.w, acc[7]);
    }
#pragma unroll
    for (int e = 0; e < NE; e++) {
#pragma unroll
        for (int o = 16; o; o >>= 1)
            acc[e] += __shfl_xor_sync(0xffffffffu, acc[e], o);
    }

    float s[NE];
#pragma unroll
    for (int e = 0; e < NE; e++) s[e] = acc[e] + __ldg(gb + e);

    // top-3 scan; strict '>' keeps lowest index on ties (matches jax top_k)
    float v1 = -1e30f, v2 = -1e30f, v3 = -1e30f;
    int i1 = 0, i2 = 0;
#pragma unroll
    for (int e = 0; e < NE; e++) {
        float se = s[e];
        if (se > v1)      { v3 = v2; v2 = v1; i2 = i1; v1 = se; i1 = e; }
        else if (se > v2) { v3 = v2; v2 = se; i2 = e; }
        else if (se > v3) { v3 = se; }
    }

    // If the selection boundary is numerically tight, recompute in fp64.
    if (v2 - v3 < 1e-4f) {
        double da[NE];
#pragma unroll
        for (int e = 0; e < NE; e++) da[e] = 0.0;
        for (int d = lane; d < DM; d += 32) {
            double xv = (double)xr[d];
#pragma unroll
            for (int e = 0; e < NE; e++)
                da[e] = fma(xv, (double)gw[d * NE + e], da[e]);
        }
#pragma unroll
        for (int e = 0; e < NE; e++) {
#pragma unroll
            for (int o = 16; o; o >>= 1)
                da[e] += __shfl_xor_sync(0xffffffffu, da[e], o);
        }
#pragma unroll
        for (int e = 0; e < NE; e++) s[e] = (float)(da[e] + (double)gb[e]);
        v1 = -1e30f; v2 = -1e30f; i1 = 0; i2 = 0;
#pragma unroll
        for (int e = 0; e < NE; e++) {
            float se = s[e];
            if (se > v1)      { v2 = v1; i2 = i1; v1 = se; i1 = e; }
            else if (se > v2) { v2 = se; i2 = e; }
        }
    }

    if (lane == 0) {
        int sl = atomicAdd(&g_count[i1], 1);
        g_tokens[i1][sl] = gwid;
        g_scales[i1][sl] = v1;
        sl = atomicAdd(&g_count[i2], 1);
        g_tokens[i2][sl] = gwid;
        g_scales[i2][sl] = v2;
    }
}

__global__ void prefix_kernel() {
    if (threadIdx.x == 0) {
        int off = 0;
#pragma unroll
        for (int e = 0; e < NE; e++) { g_offsets[e] = off; off += g_count[e]; }
    }
}

// ---------------- grouped GEMM (tf32 mma.sync, 128x128x32 tiles) ----------------
// MODE 0: h = relu(gather(x) @ w1[e] + b1[e])  -> g_h
// MODE 1: out[tok] += scale * (g_h @ w2[e] + b2[e])   (atomic scatter)
#define AS_STRIDE 36
#define BS_STRIDE 136
#define AS_WORDS (128 * AS_STRIDE)   // 4608
#define BS_WORDS (32 * BS_STRIDE)    // 4352
#define SMEM_WORDS (2 * (AS_WORDS + BS_WORDS))
#define SMEM_BYTES (SMEM_WORDS * 4)  // 71680

template <int MODE>
__global__ __launch_bounds__(256, 2)
void moe_gemm(const float* __restrict__ Asrc, const float* __restrict__ W,
              const float* __restrict__ bias, float* __restrict__ Out) {
    const int e = blockIdx.z;
    const int rows = g_count[e];
    const int m0 = blockIdx.x * 128;
    if (m0 >= rows) return;
    const int n0 = blockIdx.y * 128;
    const int gOff = g_offsets[e];
    const float* We = W + (size_t)e * (DM * HD);
    const float* be = bias + e * 1024;

    extern __shared__ unsigned sm[];
    unsigned* AsBase = sm;
    unsigned* BsBase = sm + 2 * AS_WORDS;

    const int tid = threadIdx.x;
    const int lane = tid & 31;
    const int warp = tid >> 5;
    const int wm = warp & 3;      // 4 warps along M
    const int wn = warp >> 2;     // 2 warps along N
    const int grp = lane >> 2;
    const int tg = lane & 3;

    // A staging: 256 threads, float4 each, 32 rows per pass, 4 passes
    const int arow = tid >> 3;          // 0..31
    const int acol = (tid & 7) << 2;    // 0..28

    const float* aPtr[4];
#pragma unroll
    for (int i = 0; i < 4; i++) {
        int r = arow + i * 32;
        bool v = (m0 + r) < rows;
        if (MODE == 0) {
            int tok = v ? g_tokens[e][m0 + r] : g_tokens[e][m0];
            aPtr[i] = Asrc + (size_t)tok * DM + acol;
        } else {
            int rr = v ? (gOff + m0 + r) : (gOff + m0);
            aPtr[i] = g_h + (size_t)rr * DM + acol;
        }
    }

    float4 aReg[4], bReg[4];

    auto loadChunk = [&](int kc) {
#pragma unroll
        for (int i = 0; i < 4; i++)
            aReg[i] = *(const float4*)(aPtr[i] + kc * 32);
#pragma unroll
        for (int i = 0; i < 4; i++) {
            int f = tid + i * 256;
            int kr = f >> 5;
            int cc = (f & 31) << 2;
            bReg[i] = *(const float4*)(We + (size_t)(kc * 32 + kr) * 1024 + n0 + cc);
        }
    };
    auto storeChunk = [&](int buf) {
        unsigned* A = AsBase + buf * AS_WORDS;
#pragma unroll
        for (int i = 0; i < 4; i++) {
            int r = arow + i * 32;
            uint4 v = make_uint4(f2tf(aReg[i].x), f2tf(aReg[i].y),
                                 f2tf(aReg[i].z), f2tf(aReg[i].w));
            *(uint4*)(A + r * AS_STRIDE + acol) = v;
        }
        unsigned* Bb = BsBase + buf * BS_WORDS;
#pragma unroll
        for (int i = 0; i < 4; i++) {
            int f = tid + i * 256;
            int kr = f >> 5;
            int cc = (f & 31) << 2;
            uint4 v = make_uint4(f2tf(bReg[i].x), f2tf(bReg[i].y),
                                 f2tf(bReg[i].z), f2tf(bReg[i].w));
            *(uint4*)(Bb + kr * BS_STRIDE + cc) = v;
        }
    };

    float c[2][8][4];
#pragma unroll
    for (int mi = 0; mi < 2; mi++)
#pragma unroll
        for (int ni = 0; ni < 8; ni++)
#pragma unroll
            for (int q = 0; q < 4; q++) c[mi][ni][q] = 0.f;

    loadChunk(0);
    storeChunk(0);
    __syncthreads();

    const int NKC = DM / 32;  // 32 chunks
    for (int kc = 0; kc < NKC; kc++) {
        int buf = kc & 1;
        if (kc + 1 < NKC) loadChunk(kc + 1);

        unsigned* A = AsBase + buf * AS_WORDS;
        unsigned* Bb = BsBase + buf * BS_WORDS;
#pragma unroll
        for (int ks = 0; ks < 4; ks++) {
            unsigned a[2][4];
#pragma unroll
            for (int mi = 0; mi < 2; mi++) {
                int r = wm * 32 + mi * 16 + grp;
                int cb = ks * 8 + tg;
                a[mi][0] = A[r * AS_STRIDE + cb];
                a[mi][1] = A[(r + 8) * AS_STRIDE + cb];
                a[mi][2] = A[r * AS_STRIDE + cb + 4];
                a[mi][3] = A[(r + 8) * AS_STRIDE + cb + 4];
            }
#pragma unroll
            for (int ni = 0; ni < 8; ni++) {
                unsigned b[2];
                int k = ks * 8 + tg;
                int n = wn * 64 + ni * 8 + grp;
                b[0] = Bb[k * BS_STRIDE + n];
                b[1] = Bb[(k + 4) * BS_STRIDE + n];
                mma8(c[0][ni], a[0], b);
                mma8(c[1][ni], a[1], b);
            }
        }
        if (kc + 1 < NKC) storeChunk(buf ^ 1);
        __syncthreads();
    }

    // epilogue
#pragma unroll
    for (int mi = 0; mi < 2; mi++) {
#pragma unroll
        for (int half = 0; half < 2; half++) {
            int r = wm * 32 + mi * 16 + grp + half * 8;
            if (m0 + r >= rows) continue;
            if (MODE == 0) {
                float* orow = g_h + (size_t)(gOff + m0 + r) * HD + n0;
#pragma unroll
                for (int ni = 0; ni < 8; ni++) {
                    int col = wn * 64 + ni * 8 + tg * 2;
                    float v0 = fmaxf(c[mi][ni][half * 2 + 0] + be[n0 + col], 0.f);
                    float v1 = fmaxf(c[mi][ni][half * 2 + 1] + be[n0 + col + 1], 0.f);
                    *(float2*)(orow + col) = make_float2(v0, v1);
                }
            } else {
                int tok = g_tokens[e][m0 + r];
                float sc = g_scales[e][m0 + r];
                float* orow = Out + (size_t)tok * DM + n0;
#pragma unroll
                for (int ni = 0; ni < 8; ni++) {
                    int col = wn * 64 + ni * 8 + tg * 2;
                    atomicAdd(orow + col,
                              sc * (c[mi][ni][half * 2 + 0] + be[n0 + col]));
                    atomicAdd(orow + col + 1,
                              sc * (c[mi][ni][half * 2 + 1] + be[n0 + col + 1]));
                }
            }
        }
    }
}

// ---------------- launch ----------------
extern "C" void kernel_launch(void* const* d_in, const int* in_sizes, int n_in,
                              void* d_out, int out_size) {
    const float* x  = (const float*)d_in[0];
    const float* gw = (const float*)d_in[1];
    const float* gb = (const float*)d_in[2];
    const float* w1 = (const float*)d_in[3];
    const float* b1 = (const float*)d_in[4];
    const float* w2 = (const float*)d_in[5];
    const float* b2 = (const float*)d_in[6];
    float* out = (float*)d_out;

    cudaFuncSetAttribute(moe_gemm<0>, cudaFuncAttributeMaxDynamicSharedMemorySize, SMEM_BYTES);
    cudaFuncSetAttribute(moe_gemm<1>, cudaFuncAttributeMaxDynamicSharedMemorySize, SMEM_BYTES);

    cudaMemsetAsync(d_out, 0, (size_t)NTOK * DM * sizeof(float));
    init_kernel<<<1, 32>>>();
    gate_kernel<<<NTOK / 8, 256>>>(x, gw, gb);
    prefix_kernel<<<1, 32>>>();

    dim3 grid(NTOK / 128, HD / 128, NE);
    moe_gemm<0><<<grid, 256, SMEM_BYTES>>>(x, w1, b1, nullptr);
    moe_gemm<1><<<grid, 256, SMEM_BYTES>>>(nullptr, w2, b2, out);
}

// round 3
// speedup vs baseline: 1.0143x; 1.0143x over previous
#include <cuda_runtime.h>
#include <cstdint>

#define NTOK 32768
#define DM 1024
#define HD 1024
#define NE 8

#define BM 128
#define BN 128
#define BK 32
#define NKC (DM / BK)

// stage: A 128x32 fp32 pad-144B rows = 18432B ; B 32x128 pad-544B rows = 17408B
#define A_STG_BYTES 18432
#define B_STG_BYTES 17408
#define STG_BYTES (A_STG_BYTES + B_STG_BYTES)   // 35840
#define STAGES 3
#define SMEM_BYTES (STAGES * STG_BYTES)         // 107520 -> 2 CTA/SM

// ---------------- device scratch ----------------
__device__ int      g_count[NE];
__device__ int      g_offsets[NE];
__device__ int      g_tokens[NE][NTOK];
__device__ float    g_scales[NE][NTOK];
__device__ unsigned g_map[NTOK * 2];                    // token -> (e<<16)|slot, x2
__device__ float    g_xr[(size_t)NTOK * DM];            // tf32-rounded x
__device__ float    g_w1r[(size_t)NE * DM * HD];        // tf32-rounded w1 [E][D][H]
__device__ float    g_w2r[(size_t)NE * HD * DM];        // tf32-rounded w2 [E][H][D]
__device__ float    g_h[(size_t)2 * NTOK * HD];         // hidden, tf32-rounded
__device__ float    g_o[(size_t)2 * NTOK * DM];         // per-(expert,row) scaled output

// ---------------- helpers ----------------
__device__ __forceinline__ uint32_t smem_u32(const void* p) {
    uint32_t a;
    asm("{ .reg .u64 t; cvta.to.shared.u64 t, %1; cvt.u32.u64 %0, t; }" : "=r"(a) : "l"(p));
    return a;
}
__device__ __forceinline__ unsigned f2tf(float v) {
    unsigned o; asm("cvt.rna.tf32.f32 %0, %1;" : "=r"(o) : "f"(v)); return o;
}
__device__ __forceinline__ void mma8(float* c, const unsigned* a, const unsigned* b) {
    asm volatile(
        "mma.sync.aligned.m16n8k8.row.col.f32.tf32.tf32.f32 "
        "{%0,%1,%2,%3}, {%4,%5,%6,%7}, {%8,%9}, {%0,%1,%2,%3};\n"
        : "+f"(c[0]), "+f"(c[1]), "+f"(c[2]), "+f"(c[3])
        : "r"(a[0]), "r"(a[1]), "r"(a[2]), "r"(a[3]), "r"(b[0]), "r"(b[1]));
}
__device__ __forceinline__ void cp16(uint32_t dst, const void* src) {
    asm volatile("cp.async.cg.shared.global [%0], [%1], 16;" :: "r"(dst), "l"(src) : "memory");
}
#define CP_COMMIT() asm volatile("cp.async.commit_group;" ::: "memory")
#define CP_WAIT1()  asm volatile("cp.async.wait_group 1;" ::: "memory")

// ---------------- init / gate / prefix ----------------
__global__ void init_kernel() {
    if (threadIdx.x < NE) g_count[threadIdx.x] = 0;
}

__global__ void gate_kernel(const float* __restrict__ x,
                            const float* __restrict__ gw,
                            const float* __restrict__ gb) {
    int gwid = (blockIdx.x * blockDim.x + threadIdx.x) >> 5;
    int lane = threadIdx.x & 31;
    if (gwid >= NTOK) return;
    const float* xr = x + (size_t)gwid * DM;

    float acc[NE];
#pragma unroll
    for (int e = 0; e < NE; e++) acc[e] = 0.f;
    for (int d = lane; d < DM; d += 32) {
        float xv = __ldg(xr + d);
        const float4* w4 = (const float4*)(gw + d * NE);
        float4 w0 = __ldg(w4), w1 = __ldg(w4 + 1);
        acc[0] = fmaf(xv, w0.x, acc[0]); acc[1] = fmaf(xv, w0.y, acc[1]);
        acc[2] = fmaf(xv, w0.z, acc[2]); acc[3] = fmaf(xv, w0.w, acc[3]);
        acc[4] = fmaf(xv, w1.x, acc[4]); acc[5] = fmaf(xv, w1.y, acc[5]);
        acc[6] = fmaf(xv, w1.z, acc[6]); acc[7] = fmaf(xv, w1.w, acc[7]);
    }
#pragma unroll
    for (int e = 0; e < NE; e++)
#pragma unroll
        for (int o = 16; o; o >>= 1) acc[e] += __shfl_xor_sync(0xffffffffu, acc[e], o);

    float s[NE];
#pragma unroll
    for (int e = 0; e < NE; e++) s[e] = acc[e] + __ldg(gb + e);

    float v1 = -1e30f, v2 = -1e30f, v3 = -1e30f;
    int i1 = 0, i2 = 0;
#pragma unroll
    for (int e = 0; e < NE; e++) {
        float se = s[e];
        if (se > v1)      { v3 = v2; v2 = v1; i2 = i1; v1 = se; i1 = e; }
        else if (se > v2) { v3 = v2; v2 = se; i2 = e; }
        else if (se > v3) { v3 = se; }
    }
    if (v2 - v3 < 1e-4f) {    // tight routing boundary -> exact fp64 recompute
        double da[NE];
#pragma unroll
        for (int e = 0; e < NE; e++) da[e] = 0.0;
        for (int d = lane; d < DM; d += 32) {
            double xv = (double)xr[d];
#pragma unroll
            for (int e = 0; e < NE; e++) da[e] = fma(xv, (double)gw[d * NE + e], da[e]);
        }
#pragma unroll
        for (int e = 0; e < NE; e++)
#pragma unroll
            for (int o = 16; o; o >>= 1) da[e] += __shfl_xor_sync(0xffffffffu, da[e], o);
#pragma unroll
        for (int e = 0; e < NE; e++) s[e] = (float)(da[e] + (double)gb[e]);
        v1 = -1e30f; v2 = -1e30f; i1 = 0; i2 = 0;
#pragma unroll
        for (int e = 0; e < NE; e++) {
            float se = s[e];
            if (se > v1)      { v2 = v1; i2 = i1; v1 = se; i1 = e; }
            else if (se > v2) { v2 = se; i2 = e; }
        }
    }
    if (lane == 0) {
        int sl1 = atomicAdd(&g_count[i1], 1);
        g_tokens[i1][sl1] = gwid; g_scales[i1][sl1] = v1;
        int sl2 = atomicAdd(&g_count[i2], 1);
        g_tokens[i2][sl2] = gwid; g_scales[i2][sl2] = v2;
        g_map[2 * gwid + 0] = ((unsigned)i1 << 16) | (unsigned)sl1;
        g_map[2 * gwid + 1] = ((unsigned)i2 << 16) | (unsigned)sl2;
    }
}

__global__ void prefix_kernel() {
    if (threadIdx.x == 0) {
        int off = 0;
#pragma unroll
        for (int e = 0; e < NE; e++) { g_offsets[e] = off; off += g_count[e]; }
    }
}

// ---------------- tf32 pre-round (elementwise, float4) ----------------
__global__ void preround(const float* __restrict__ src, float* __restrict__ dst) {
    size_t i = (size_t)blockIdx.x * blockDim.x + threadIdx.x;
    float4 v = ((const float4*)src)[i];
    uint4 u = make_uint4(f2tf(v.x), f2tf(v.y), f2tf(v.z), f2tf(v.w));
    ((uint4*)dst)[i] = u;
}

// ---------------- grouped GEMM: 128x128 CTA, 4 warps of 64x64, cp.async x3 ----------------
// MODE 0: g_h = rna(relu(gather(g_xr) @ w1r + b1))
// MODE 1: g_o = scale * (g_h @ w2r + b2)
template <int MODE>
__global__ void __launch_bounds__(128, 2)
moe_gemm(const float* __restrict__ W, const float* __restrict__ bias) {
    const int e = blockIdx.z;
    const int rows = g_count[e];
    const int m0 = blockIdx.x * BM;
    if (m0 >= rows) return;
    const int n0 = blockIdx.y * BN;
    const int gOff = g_offsets[e];
    const float* We = W + ((size_t)e << 20);
    const float* be = bias + e * 1024;

    extern __shared__ char smem[];
    const uint32_t sbu = smem_u32(smem);
    unsigned* smw = (unsigned*)smem;

    const int tid = threadIdx.x;
    const int lane = tid & 31;
    const int warp = tid >> 5;
    const int wm = warp & 1;          // 2 warps along M
    const int wn = warp >> 1;         // 2 warps along N
    const int grp = lane >> 2;
    const int tg = lane & 3;

    // ---- loader thread mapping ----
    // A: thread -> (row = tid>>2 [+32i], chunk = tid&3 [+4j]); 8 cp16/thread/stage
    const int ar = tid >> 2, ac = tid & 3;
    const float* aP[4];
#pragma unroll
    for (int i = 0; i < 4; i++) {
        int r = m0 + ar + 32 * i;
        int rv = (r < rows) ? r : m0;
        if (MODE == 0) {
            int tok = g_tokens[e][rv];
            aP[i] = g_xr + (size_t)tok * DM + ac * 4;
        } else {
            aP[i] = g_h + (size_t)(gOff + rv) * DM + ac * 4;
        }
    }
    // B: thread -> (k = tid>>2, chunk = tid&3 [+4j]); 8 cp16/thread/stage
    const int bk = tid >> 2, bc = tid & 3;
    const float* bP = We + (size_t)bk * 1024 + n0 + bc * 4;

    auto issueStage = [&](int st, int kc) {
        uint32_t sa = sbu + st * STG_BYTES;
        uint32_t sbB = sa + A_STG_BYTES;
#pragma unroll
        for (int i = 0; i < 4; i++)
#pragma unroll
            for (int j = 0; j < 2; j++)
                cp16(sa + (ar + 32 * i) * 144 + (ac + 4 * j) * 16,
                     aP[i] + kc * BK + j * 16);
#pragma unroll
        for (int j = 0; j < 8; j++)
            cp16(sbB + bk * 544 + (bc + 4 * j) * 16,
                 bP + (size_t)(kc * BK) * 1024 + j * 16);
    };

    float c[4][8][4];
#pragma unroll
    for (int mi = 0; mi < 4; mi++)
#pragma unroll
        for (int ni = 0; ni < 8; ni++)
#pragma unroll
            for (int q = 0; q < 4; q++) c[mi][ni][q] = 0.f;

    issueStage(0, 0); CP_COMMIT();
    issueStage(1, 1); CP_COMMIT();

    for (int kc = 0; kc < NKC; kc++) {
        CP_WAIT1();
        __syncthreads();
        if (kc + 2 < NKC) issueStage((kc + 2) % STAGES, kc + 2);
        CP_COMMIT();

        const int st = kc % STAGES;
        unsigned* As = smw + st * (STG_BYTES / 4);
        unsigned* Bs = As + (A_STG_BYTES / 4);
#pragma unroll
        for (int ks = 0; ks < 4; ks++) {
            const int cb = ks * 8 + tg;
            unsigned a[4][4];
#pragma unroll
            for (int mi = 0; mi < 4; mi++) {
                int r = wm * 64 + mi * 16 + grp;
                a[mi][0] = As[r * 36 + cb];
                a[mi][1] = As[(r + 8) * 36 + cb];
                a[mi][2] = As[r * 36 + cb + 4];
                a[mi][3] = As[(r + 8) * 36 + cb + 4];
            }
#pragma unroll
            for (int ni = 0; ni < 8; ni++) {
                unsigned b[2];
                int n = wn * 64 + ni * 8 + grp;
                b[0] = Bs[cb * 136 + n];
                b[1] = Bs[(cb + 4) * 136 + n];
#pragma unroll
                for (int mi = 0; mi < 4; mi++) mma8(c[mi][ni], a[mi], b);
            }
        }
    }

    // ---- epilogue ----
#pragma unroll
    for (int mi = 0; mi < 4; mi++) {
#pragma unroll
        for (int half = 0; half < 2; half++) {
            int r = wm * 64 + mi * 16 + grp + half * 8;
            if (m0 + r >= rows) continue;
            if (MODE == 0) {
                float* orow = g_h + (size_t)(gOff + m0 + r) * HD + n0;
#pragma unroll
                for (int ni = 0; ni < 8; ni++) {
                    int col = wn * 64 + ni * 8 + tg * 2;
                    float v0 = fmaxf(c[mi][ni][half * 2 + 0] + __ldg(be + n0 + col), 0.f);
                    float v1 = fmaxf(c[mi][ni][half * 2 + 1] + __ldg(be + n0 + col + 1), 0.f);
                    float2 p;
                    p.x = __uint_as_float(f2tf(v0));
                    p.y = __uint_as_float(f2tf(v1));
                    *(float2*)(orow + col) = p;
                }
            } else {
                float sc = g_scales[e][m0 + r];
                float* orow = g_o + (size_t)(gOff + m0 + r) * DM + n0;
#pragma unroll
                for (int ni = 0; ni < 8; ni++) {
                    int col = wn * 64 + ni * 8 + tg * 2;
                    float2 p;
                    p.x = sc * (c[mi][ni][half * 2 + 0] + __ldg(be + n0 + col));
                    p.y = sc * (c[mi][ni][half * 2 + 1] + __ldg(be + n0 + col + 1));
                    *(float2*)(orow + col) = p;
                }
            }
        }
    }
}

// ---------------- combine: out[tok] = g_o[row1] + g_o[row2] ----------------
__global__ void combine_kernel(float* __restrict__ out) {
    int tok = blockIdx.x;
    int t = threadIdx.x;
    unsigned e0 = g_map[2 * tok], e1 = g_map[2 * tok + 1];
    int r0 = g_offsets[e0 >> 16] + (int)(e0 & 0xffffu);
    int r1 = g_offsets[e1 >> 16] + (int)(e1 & 0xffffu);
    const float4* a = (const float4*)(g_o + (size_t)r0 * DM) + t;
    const float4* b = (const float4*)(g_o + (size_t)r1 * DM) + t;
    float4 va = *a, vb = *b;
    float4 o = make_float4(va.x + vb.x, va.y + vb.y, va.z + vb.z, va.w + vb.w);
    ((float4*)(out + (size_t)tok * DM))[t] = o;
}

// ---------------- launch ----------------
extern "C" void kernel_launch(void* const* d_in, const int* in_sizes, int n_in,
                              void* d_out, int out_size) {
    const float* x  = (const float*)d_in[0];
    const float* gw = (const float*)d_in[1];
    const float* gb = (const float*)d_in[2];
    const float* w1 = (const float*)d_in[3];
    const float* b1 = (const float*)d_in[4];
    const float* w2 = (const float*)d_in[5];
    const float* b2 = (const float*)d_in[6];
    float* out = (float*)d_out;

    cudaFuncSetAttribute(moe_gemm<0>, cudaFuncAttributeMaxDynamicSharedMemorySize, SMEM_BYTES);
    cudaFuncSetAttribute(moe_gemm<1>, cudaFuncAttributeMaxDynamicSharedMemorySize, SMEM_BYTES);

    init_kernel<<<1, 32>>>();
    gate_kernel<<<NTOK / 8, 256>>>(x, gw, gb);
    prefix_kernel<<<1, 32>>>();

    float* xr_p;  cudaGetSymbolAddress((void**)&xr_p,  g_xr);
    float* w1r_p; cudaGetSymbolAddress((void**)&w1r_p, g_w1r);
    float* w2r_p; cudaGetSymbolAddress((void**)&w2r_p, g_w2r);

    preround<<<(NTOK * DM / 4) / 256, 256>>>(x, xr_p);
    preround<<<(NE * DM * HD / 4) / 256, 256>>>(w1, w1r_p);
    preround<<<(NE * HD * DM / 4) / 256, 256>>>(w2, w2r_p);

    dim3 grid(NTOK / BM, HD / BN, NE);
    moe_gemm<0><<<grid, 128, SMEM_BYTES>>>(w1r_p, b1);
    moe_gemm<1><<<grid, 128, SMEM_BYTES>>>(w2r_p, b2);

    combine_kernel<<<NTOK, 256>>>(out);
}

// round 4
// speedup vs baseline: 1.6889x; 1.6651x over previous
#include <cuda_runtime.h>
#include <cuda_fp16.h>
#include <cstdint>

#define NTOK 32768
#define DM 1024
#define HD 1024
#define NE 8

#define BM 128
#define BN 128
#define BKH 64                  // k per chunk (halves) = 128 bytes/row
#define NKC (DM / BKH)          // 16 chunks

#define A_STG_BYTES (BM * 128)  // 16384
#define B_STG_BYTES (BN * 128)  // 16384
#define STG_BYTES (A_STG_BYTES + B_STG_BYTES)   // 32768
#define STAGES 3
#define SMEM_BYTES (STAGES * STG_BYTES)         // 98304 -> 2 CTA/SM

// ---------------- device scratch ----------------
__device__ int      g_count[NE];
__device__ int      g_offsets[NE];
__device__ int      g_tokens[NE][NTOK];
__device__ float    g_scales[NE][NTOK];
__device__ unsigned g_map[NTOK * 2];                 // token -> (e<<16)|slot, x2
__device__ __half   g_xh[(size_t)NTOK * DM];         // half x
__device__ __half   g_w1h[(size_t)NE * HD * DM];     // w1^T [E][H][D] half
__device__ __half   g_w2h[(size_t)NE * DM * HD];     // w2^T [E][D][H] half
__device__ __half   g_h[(size_t)2 * NTOK * HD];      // hidden half
__device__ float    g_o[(size_t)2 * NTOK * DM];      // per-(expert,row) scaled out

// ---------------- helpers ----------------
__device__ __forceinline__ uint32_t smem_u32(const void* p) {
    uint32_t a;
    asm("{ .reg .u64 t; cvta.to.shared.u64 t, %1; cvt.u32.u64 %0, t; }" : "=r"(a) : "l"(p));
    return a;
}
__device__ __forceinline__ void cp16(uint32_t dst, const void* src) {
    asm volatile("cp.async.cg.shared.global [%0], [%1], 16;" :: "r"(dst), "l"(src) : "memory");
}
#define CP_COMMIT() asm volatile("cp.async.commit_group;" ::: "memory")
#define CP_WAIT1()  asm volatile("cp.async.wait_group 1;" ::: "memory")

#define LDSM4(r0, r1, r2, r3, addr) \
    asm volatile("ldmatrix.sync.aligned.m8n8.x4.shared.b16 {%0,%1,%2,%3}, [%4];" \
        : "=r"(r0), "=r"(r1), "=r"(r2), "=r"(r3) : "r"(addr))

__device__ __forceinline__ void mma16(float* c, const uint32_t* a, const uint32_t* b) {
    asm volatile(
        "mma.sync.aligned.m16n8k16.row.col.f32.f16.f16.f32 "
        "{%0,%1,%2,%3}, {%4,%5,%6,%7}, {%8,%9}, {%0,%1,%2,%3};\n"
        : "+f"(c[0]), "+f"(c[1]), "+f"(c[2]), "+f"(c[3])
        : "r"(a[0]), "r"(a[1]), "r"(a[2]), "r"(a[3]), "r"(b[0]), "r"(b[1]));
}

// ---------------- init / gate / prefix ----------------
__global__ void init_kernel() {
    if (threadIdx.x < NE) g_count[threadIdx.x] = 0;
}

__global__ void gate_kernel(const float* __restrict__ x,
                            const float* __restrict__ gw,
                            const float* __restrict__ gb) {
    int gwid = (blockIdx.x * blockDim.x + threadIdx.x) >> 5;
    int lane = threadIdx.x & 31;
    if (gwid >= NTOK) return;
    const float* xr = x + (size_t)gwid * DM;

    float acc[NE];
#pragma unroll
    for (int e = 0; e < NE; e++) acc[e] = 0.f;
    for (int d = lane; d < DM; d += 32) {
        float xv = __ldg(xr + d);
        const float4* w4 = (const float4*)(gw + d * NE);
        float4 w0 = __ldg(w4), w1 = __ldg(w4 + 1);
        acc[0] = fmaf(xv, w0.x, acc[0]); acc[1] = fmaf(xv, w0.y, acc[1]);
        acc[2] = fmaf(xv, w0.z, acc[2]); acc[3] = fmaf(xv, w0.w, acc[3]);
        acc[4] = fmaf(xv, w1.x, acc[4]); acc[5] = fmaf(xv, w1.y, acc[5]);
        acc[6] = fmaf(xv, w1.z, acc[6]); acc[7] = fmaf(xv, w1.w, acc[7]);
    }
#pragma unroll
    for (int e = 0; e < NE; e++)
#pragma unroll
        for (int o = 16; o; o >>= 1) acc[e] += __shfl_xor_sync(0xffffffffu, acc[e], o);

    float s[NE];
#pragma unroll
    for (int e = 0; e < NE; e++) s[e] = acc[e] + __ldg(gb + e);

    float v1 = -1e30f, v2 = -1e30f, v3 = -1e30f;
    int i1 = 0, i2 = 0;
#pragma unroll
    for (int e = 0; e < NE; e++) {
        float se = s[e];
        if (se > v1)      { v3 = v2; v2 = v1; i2 = i1; v1 = se; i1 = e; }
        else if (se > v2) { v3 = v2; v2 = se; i2 = e; }
        else if (se > v3) { v3 = se; }
    }
    if (v2 - v3 < 1e-4f) {    // tight routing boundary -> exact fp64 recompute
        double da[NE];
#pragma unroll
        for (int e = 0; e < NE; e++) da[e] = 0.0;
        for (int d = lane; d < DM; d += 32) {
            double xv = (double)xr[d];
#pragma unroll
            for (int e = 0; e < NE; e++) da[e] = fma(xv, (double)gw[d * NE + e], da[e]);
        }
#pragma unroll
        for (int e = 0; e < NE; e++)
#pragma unroll
            for (int o = 16; o; o >>= 1) da[e] += __shfl_xor_sync(0xffffffffu, da[e], o);
#pragma unroll
        for (int e = 0; e < NE; e++) s[e] = (float)(da[e] + (double)gb[e]);
        v1 = -1e30f; v2 = -1e30f; i1 = 0; i2 = 0;
#pragma unroll
        for (int e = 0; e < NE; e++) {
            float se = s[e];
            if (se > v1)      { v2 = v1; i2 = i1; v1 = se; i1 = e; }
            else if (se > v2) { v2 = se; i2 = e; }
        }
    }
    if (lane == 0) {
        int sl1 = atomicAdd(&g_count[i1], 1);
        g_tokens[i1][sl1] = gwid; g_scales[i1][sl1] = v1;
        int sl2 = atomicAdd(&g_count[i2], 1);
        g_tokens[i2][sl2] = gwid; g_scales[i2][sl2] = v2;
        g_map[2 * gwid + 0] = ((unsigned)i1 << 16) | (unsigned)sl1;
        g_map[2 * gwid + 1] = ((unsigned)i2 << 16) | (unsigned)sl2;
    }
}

__global__ void prefix_kernel() {
    if (threadIdx.x == 0) {
        int off = 0;
#pragma unroll
        for (int e = 0; e < NE; e++) { g_offsets[e] = off; off += g_count[e]; }
    }
}

// ---------------- conversions ----------------
__global__ void conv_x(const float* __restrict__ src, __half* __restrict__ dst) {
    size_t i = (size_t)blockIdx.x * blockDim.x + threadIdx.x;
    float4 v = ((const float4*)src)[i];
    __half2 h0 = __floats2half2_rn(v.x, v.y);
    __half2 h1 = __floats2half2_rn(v.z, v.w);
    ((__half2*)dst)[2 * i]     = h0;
    ((__half2*)dst)[2 * i + 1] = h1;
}

// transpose 1024x1024 per expert, fp32 -> half; z: 0-7 = w1, 8-15 = w2
__global__ void transpose_w(const float* __restrict__ w1, const float* __restrict__ w2) {
    __shared__ float t[32][33];
    int z = blockIdx.z;
    const float* src; __half* dst;
    if (z < NE) { src = w1 + ((size_t)z << 20); dst = g_w1h + ((size_t)z << 20); }
    else        { src = w2 + ((size_t)(z - NE) << 20); dst = g_w2h + ((size_t)(z - NE) << 20); }
    int bx = blockIdx.x * 32, by = blockIdx.y * 32;
    int tx = threadIdx.x, ty = threadIdx.y;
#pragma unroll
    for (int i = 0; i < 4; i++)
        t[ty + 8 * i][tx] = src[(size_t)(by + ty + 8 * i) * 1024 + bx + tx];
    __syncthreads();
#pragma unroll
    for (int i = 0; i < 4; i++)
        dst[(size_t)(bx + ty + 8 * i) * 1024 + by + tx] = __float2half_rn(t[tx][ty + 8 * i]);
}

// ---------------- fp16 grouped GEMM: 128x128 CTA, 8 warps (64x32 each) ----------------
// MODE 0: g_h = half(relu(gather(g_xh) @ g_w1h^T + b1))
// MODE 1: g_o = scale * (g_h @ g_w2h^T + b2)      (fp32, packed rows)
template <int MODE>
__global__ void __launch_bounds__(256, 2)
moe_gemm(const __half* __restrict__ W, const float* __restrict__ bias) {
    const int e = blockIdx.z;
    const int rows = g_count[e];
    const int m0 = blockIdx.x * BM;
    if (m0 >= rows) return;
    const int n0 = blockIdx.y * BN;
    const int gOff = g_offsets[e];
    const __half* We = W + ((size_t)e << 20);
    const float* be = bias + e * 1024;

    extern __shared__ char smem[];
    const uint32_t sbu = smem_u32(smem);

    const int tid = threadIdx.x;
    const int lane = tid & 31;
    const int warp = tid >> 5;
    const int wm = warp & 1;      // 2 warps along M (64 rows each)
    const int wn = warp >> 1;     // 4 warps along N (32 cols each)

    // ---- loaders: row = tid>>1 (0..127), chunks (tid&1)*4 .. +3 ----
    const int lr = tid >> 1;
    const int lcb = (tid & 1) * 4;
    const __half* aSrc;
    {
        int r = m0 + lr;
        int rv = (r < rows) ? r : m0;
        if (MODE == 0) {
            int tok = g_tokens[e][rv];
            aSrc = g_xh + (size_t)tok * DM + lcb * 8;
        } else {
            aSrc = g_h + (size_t)(gOff + rv) * DM + lcb * 8;
        }
    }
    const __half* bSrc = We + (size_t)(n0 + lr) * DM + lcb * 8;
    uint32_t aDst[4], bDst[4];
#pragma unroll
    for (int j = 0; j < 4; j++) {
        int sw = ((lcb + j) ^ (lr & 7)) * 16;
        aDst[j] = lr * 128 + sw;
        bDst[j] = A_STG_BYTES + lr * 128 + sw;
    }

    auto issueStage = [&](int st, int kc) {
        uint32_t base = sbu + st * STG_BYTES;
#pragma unroll
        for (int j = 0; j < 4; j++) {
            cp16(base + aDst[j], aSrc + (size_t)kc * BKH + j * 8);
            cp16(base + bDst[j], bSrc + (size_t)kc * BKH + j * 8);
        }
    };

    // ---- per-lane ldmatrix row offsets (stage-relative) ----
    const int rsw = lane & 7;            // swizzle xor for this lane's rows
    const int khiA = lane >> 4;          // 0/1 -> k-halves 0-7 / 8-15
    const int khiB = (lane >> 3) & 1;
    uint32_t aRow[4], bRow[2];
#pragma unroll
    for (int mi = 0; mi < 4; mi++)
        aRow[mi] = (wm * 64 + mi * 16 + (lane & 15)) * 128;
#pragma unroll
    for (int nb = 0; nb < 2; nb++)
        bRow[nb] = A_STG_BYTES +
                   (wn * 32 + nb * 16 + (lane & 7) + ((lane >> 4) & 1) * 8) * 128;

    float c[4][4][4];
#pragma unroll
    for (int mi = 0; mi < 4; mi++)
#pragma unroll
        for (int ni = 0; ni < 4; ni++)
#pragma unroll
            for (int q = 0; q < 4; q++) c[mi][ni][q] = 0.f;

    issueStage(0, 0); CP_COMMIT();
    issueStage(1, 1); CP_COMMIT();

    for (int kc = 0; kc < NKC; kc++) {
        CP_WAIT1();
        __syncthreads();
        if (kc + 2 < NKC) issueStage((kc + 2) % STAGES, kc + 2);
        CP_COMMIT();

        const uint32_t stb = sbu + (kc % STAGES) * STG_BYTES;
#pragma unroll
        for (int ks = 0; ks < 4; ks++) {
            const uint32_t swA = (uint32_t)(((ks * 2 + khiA) ^ rsw) << 4);
            const uint32_t swB = (uint32_t)(((ks * 2 + khiB) ^ rsw) << 4);
            uint32_t a[4][4];
#pragma unroll
            for (int mi = 0; mi < 4; mi++)
                LDSM4(a[mi][0], a[mi][1], a[mi][2], a[mi][3], stb + aRow[mi] + swA);
            uint32_t b[4][2];
            LDSM4(b[0][0], b[0][1], b[1][0], b[1][1], stb + bRow[0] + swB);
            LDSM4(b[2][0], b[2][1], b[3][0], b[3][1], stb + bRow[1] + swB);
#pragma unroll
            for (int mi = 0; mi < 4; mi++)
#pragma unroll
                for (int ni = 0; ni < 4; ni++)
                    mma16(c[mi][ni], a[mi], b[ni]);
        }
        __syncthreads();
    }

    // ---- epilogue ----
    const int grp = lane >> 2;
    const int tg = lane & 3;
#pragma unroll
    for (int mi = 0; mi < 4; mi++) {
#pragma unroll
        for (int half = 0; half < 2; half++) {
            int r = wm * 64 + mi * 16 + grp + half * 8;
            if (m0 + r >= rows) continue;
            if (MODE == 0) {
                __half* orow = g_h + (size_t)(gOff + m0 + r) * HD + n0;
#pragma unroll
                for (int ni = 0; ni < 4; ni++) {
                    int col = wn * 32 + ni * 8 + tg * 2;
                    float v0 = fmaxf(c[mi][ni][half * 2 + 0] + __ldg(be + n0 + col), 0.f);
                    float v1 = fmaxf(c[mi][ni][half * 2 + 1] + __ldg(be + n0 + col + 1), 0.f);
                    *(__half2*)(orow + col) = __floats2half2_rn(v0, v1);
                }
            } else {
                float sc = g_scales[e][m0 + r];
                float* orow = g_o + (size_t)(gOff + m0 + r) * DM + n0;
#pragma unroll
                for (int ni = 0; ni < 4; ni++) {
                    int col = wn * 32 + ni * 8 + tg * 2;
                    float2 p;
                    p.x = sc * (c[mi][ni][half * 2 + 0] + __ldg(be + n0 + col));
                    p.y = sc * (c[mi][ni][half * 2 + 1] + __ldg(be + n0 + col + 1));
                    *(float2*)(orow + col) = p;
                }
            }
        }
    }
}

// ---------------- combine: out[tok] = g_o[row1] + g_o[row2] ----------------
__global__ void combine_kernel(float* __restrict__ out) {
    int tok = blockIdx.x;
    int t = threadIdx.x;
    unsigned e0 = g_map[2 * tok], e1 = g_map[2 * tok + 1];
    int r0 = g_offsets[e0 >> 16] + (int)(e0 & 0xffffu);
    int r1 = g_offsets[e1 >> 16] + (int)(e1 & 0xffffu);
    const float4* a = (const float4*)(g_o + (size_t)r0 * DM) + t;
    const float4* b = (const float4*)(g_o + (size_t)r1 * DM) + t;
    float4 va = *a, vb = *b;
    float4 o = make_float4(va.x + vb.x, va.y + vb.y, va.z + vb.z, va.w + vb.w);
    ((float4*)(out + (size_t)tok * DM))[t] = o;
}

// ---------------- launch ----------------
extern "C" void kernel_launch(void* const* d_in, const int* in_sizes, int n_in,
                              void* d_out, int out_size) {
    const float* x  = (const float*)d_in[0];
    const float* gw = (const float*)d_in[1];
    const float* gb = (const float*)d_in[2];
    const float* w1 = (const float*)d_in[3];
    const float* b1 = (const float*)d_in[4];
    const float* w2 = (const float*)d_in[5];
    const float* b2 = (const float*)d_in[6];
    float* out = (float*)d_out;

    cudaFuncSetAttribute(moe_gemm<0>, cudaFuncAttributeMaxDynamicSharedMemorySize, SMEM_BYTES);
    cudaFuncSetAttribute(moe_gemm<1>, cudaFuncAttributeMaxDynamicSharedMemorySize, SMEM_BYTES);

    init_kernel<<<1, 32>>>();
    gate_kernel<<<NTOK / 8, 256>>>(x, gw, gb);
    prefix_kernel<<<1, 32>>>();

    __half* xh_p; cudaGetSymbolAddress((void**)&xh_p, g_xh);
    conv_x<<<(NTOK * DM / 4) / 256, 256>>>(x, xh_p);
    transpose_w<<<dim3(32, 32, 16), dim3(32, 8)>>>(w1, w2);

    __half* w1h_p; cudaGetSymbolAddress((void**)&w1h_p, g_w1h);
    __half* w2h_p; cudaGetSymbolAddress((void**)&w2h_p, g_w2h);

    dim3 grid(NTOK / BM, HD / BN, NE);
    moe_gemm<0><<<grid, 256, SMEM_BYTES>>>(w1h_p, b1);
    moe_gemm<1><<<grid, 256, SMEM_BYTES>>>(w2h_p, b2);

    combine_kernel<<<NTOK, 256>>>(out);
}